// round 16
// baseline (speedup 1.0000x reference)
#include <cuda_runtime.h>
#include <cuda_bf16.h>
#include <cuda_fp16.h>
#include <cstdint>

#define N_NODES 50000
#define E_ORIG  800000
#define E_TOT   850000   // E_ORIG + N self-loops (both divisible by 4)
#define NBLK    196      // ceil(N_NODES/256)
#define N_HALF  25088    // 196 * 128 (gemm2 block multiple)
#define FULLMASK 0xffffffffu

// ---------------- scratch (static __device__ — no allocation) ----------------
__device__ __align__(16) int   g_srcs [E_TOT];        // src sorted by dst (CSR)
__device__ __align__(16) int   g_deg[N_NODES];
__device__ __align__(16) int   g_rowstart[N_NODES + 1];
__device__ __align__(16) int   g_cursor[N_NODES];
__device__ __align__(16) int   g_blocksum[NBLK];
__device__ __align__(16) int   g_blockoff[NBLK];
__device__ __align__(16) __half g_h1h[N_NODES * 128]; // fp16 mirror of x @ W1 (gather only)
__device__ __align__(16) float g_as1 [N_NODES * 4];
__device__ __align__(16) float g_ad1 [N_NODES * 4];
__device__ __align__(16) float g_out1[N_NODES * 128]; // relu(agg1 + b1)
__device__ __align__(16) __half g_h2h[N_NODES * 64];  // fp16 mirror of out1 @ W2
__device__ __align__(16) float g_as2 [N_NODES];
__device__ __align__(16) float g_ad2 [N_NODES];

__device__ __forceinline__ float lrelu(float v) {
    return v > 0.f ? v : 0.2f * v;
}

// packed f32x2 helpers (FFMA2 — ptxas never emits it from C++)
__device__ __forceinline__ unsigned long long pack_dup(float a) {
    unsigned long long r;
    asm("mov.b64 %0, {%1, %1};" : "=l"(r) : "f"(a));
    return r;
}
__device__ __forceinline__ void ffma2(unsigned long long& acc,
                                      unsigned long long a,
                                      unsigned long long b) {
    asm("fma.rn.f32x2 %0, %1, %2, %0;" : "+l"(acc) : "l"(a), "l"(b));
}
__device__ __forceinline__ float2 unpack2(unsigned long long v) {
    float lo, hi;
    asm("mov.b64 {%0, %1}, %2;" : "=f"(lo), "=f"(hi) : "l"(v));
    return make_float2(lo, hi);
}
__device__ __forceinline__ uint32_t h2_bits(__half2 h) {
    uint32_t u;
    memcpy(&u, &h, 4);
    return u;
}

// ---------------- CSR build ----------------
// edge_index is INT32 (JAX x64 disabled downcasts int64 -> int32)
__global__ void build_deg_kernel(const int* __restrict__ ei) {
    int e = (blockIdx.x * blockDim.x + threadIdx.x) * 4;
    if (e >= E_TOT) return;
    int4 d4;
    if (e < E_ORIG) {
        d4 = *(const int4*)&ei[E_ORIG + e];
    } else {
        int b = e - E_ORIG;
        d4 = make_int4(b, b + 1, b + 2, b + 3);
    }
    if ((unsigned)d4.x < (unsigned)N_NODES) atomicAdd(&g_deg[d4.x], 1);
    if ((unsigned)d4.y < (unsigned)N_NODES) atomicAdd(&g_deg[d4.y], 1);
    if ((unsigned)d4.z < (unsigned)N_NODES) atomicAdd(&g_deg[d4.z], 1);
    if ((unsigned)d4.w < (unsigned)N_NODES) atomicAdd(&g_deg[d4.w], 1);
}

// parallel scan stage 1: per-block exclusive scan (partial) + block sums
__global__ void scan1_kernel() {
    __shared__ int wsum[8], woff[8];
    int tid = threadIdx.x, lane = tid & 31, wid = tid >> 5;
    int i = blockIdx.x * 256 + tid;
    int v = (i < N_NODES) ? g_deg[i] : 0;
    int x = v;
    #pragma unroll
    for (int off = 1; off < 32; off <<= 1) {
        int t = __shfl_up_sync(FULLMASK, x, off);
        if (lane >= off) x += t;
    }
    if (lane == 31) wsum[wid] = x;
    __syncthreads();
    if (wid == 0 && lane < 8) {
        int s = wsum[lane];
        int y = s;
        #pragma unroll
        for (int off = 1; off < 8; off <<= 1) {
            int t = __shfl_up_sync(0xffu, y, off);
            if (lane >= off) y += t;
        }
        woff[lane] = y - s;
        if (lane == 7) g_blocksum[blockIdx.x] = y;
    }
    __syncthreads();
    if (i < N_NODES) g_rowstart[i] = woff[wid] + (x - v);   // partial (in-block)
}

// stage 2: single-block exclusive scan of NBLK block sums
__global__ void scan2_kernel() {
    __shared__ int wsum[8], woff[8];
    int tid = threadIdx.x, lane = tid & 31, wid = tid >> 5;
    int v = (tid < NBLK) ? g_blocksum[tid] : 0;
    int x = v;
    #pragma unroll
    for (int off = 1; off < 32; off <<= 1) {
        int t = __shfl_up_sync(FULLMASK, x, off);
        if (lane >= off) x += t;
    }
    if (lane == 31) wsum[wid] = x;
    __syncthreads();
    if (wid == 0 && lane < 8) {
        int s = wsum[lane];
        int y = s;
        #pragma unroll
        for (int off = 1; off < 8; off <<= 1) {
            int t = __shfl_up_sync(0xffu, y, off);
            if (lane >= off) y += t;
        }
        woff[lane] = y - s;
        if (lane == 7) g_rowstart[N_NODES] = y;   // total = E_TOT
    }
    __syncthreads();
    if (tid < NBLK) g_blockoff[tid] = woff[wid] + (x - v);
}

// stage 3: add block offsets -> final rowstart + cursor
__global__ void scan3_kernel() {
    int i = blockIdx.x * 256 + threadIdx.x;
    if (i < N_NODES) {
        int r = g_rowstart[i] + g_blockoff[blockIdx.x];
        g_rowstart[i] = r;
        g_cursor[i] = r;
    }
}

__global__ void scatter_kernel(const int* __restrict__ ei) {
    int e = (blockIdx.x * blockDim.x + threadIdx.x) * 4;
    if (e >= E_TOT) return;
    int4 s4, d4;
    if (e < E_ORIG) {
        s4 = *(const int4*)&ei[e];
        d4 = *(const int4*)&ei[E_ORIG + e];
    } else {
        int b = e - E_ORIG;
        s4 = make_int4(b, b + 1, b + 2, b + 3);
        d4 = s4;
    }
    #pragma unroll
    for (int l = 0; l < 4; l++) {
        int d = (l == 0) ? d4.x : (l == 1) ? d4.y : (l == 2) ? d4.z : d4.w;
        int s = (l == 0) ? s4.x : (l == 1) ? s4.y : (l == 2) ? s4.z : s4.w;
        if ((unsigned)d < (unsigned)N_NODES) {
            int pos = atomicAdd(&g_cursor[d], 1);
            if ((unsigned)pos < (unsigned)E_TOT) g_srcs[pos] = s;
        }
    }
}

// ---- GEMM1: h1 = x @ W1 (FFMA2, sw-pipelined) + fused alpha1 + fp16 mirror -
__global__ __launch_bounds__(256, 2) void gemm1_kernel(const float* __restrict__ X,
                                                       const float* __restrict__ W,
                                                       const float* __restrict__ a_src,
                                                       const float* __restrict__ a_dst) {
    __shared__ __align__(16) float As[16][132];
    __shared__ __align__(16) float Bs[16][128];
    int tid = threadIdx.x;
    int tx = tid & 15, ty = tid >> 4;
    int blockRow = blockIdx.x * 128;
    unsigned long long accp[8][4];
    #pragma unroll
    for (int i = 0; i < 8; i++)
        #pragma unroll
        for (int j = 0; j < 4; j++) accp[i][j] = 0ull;

    int id0 = tid * 2, id1 = tid * 2 + 1;
    int xr0 = id0 >> 2, xc0 = (id0 & 3) * 4;
    int xr1 = id1 >> 2, xc1 = (id1 & 3) * 4;
    int wr0 = id0 >> 5, wc0 = (id0 & 31) * 4;
    int wr1 = id1 >> 5, wc1 = (id1 & 31) * 4;
    int grow0 = blockRow + xr0, grow1 = blockRow + xr1;

    float4 xa0 = make_float4(0, 0, 0, 0), xa1 = make_float4(0, 0, 0, 0);
    if (grow0 < N_NODES) xa0 = *(const float4*)&X[grow0 * 128 + xc0];
    if (grow1 < N_NODES) xa1 = *(const float4*)&X[grow1 * 128 + xc1];
    float4 wb0 = *(const float4*)&W[wr0 * 128 + wc0];
    float4 wb1 = *(const float4*)&W[wr1 * 128 + wc1];

    for (int k0 = 0; k0 < 128; k0 += 16) {
        As[xc0 + 0][xr0] = xa0.x; As[xc0 + 1][xr0] = xa0.y;
        As[xc0 + 2][xr0] = xa0.z; As[xc0 + 3][xr0] = xa0.w;
        As[xc1 + 0][xr1] = xa1.x; As[xc1 + 1][xr1] = xa1.y;
        As[xc1 + 2][xr1] = xa1.z; As[xc1 + 3][xr1] = xa1.w;
        *(float4*)&Bs[wr0][wc0] = wb0;
        *(float4*)&Bs[wr1][wc1] = wb1;
        __syncthreads();
        if (k0 + 16 < 128) {   // prefetch next tile while computing this one
            int kn = k0 + 16;
            if (grow0 < N_NODES) xa0 = *(const float4*)&X[grow0 * 128 + kn + xc0];
            if (grow1 < N_NODES) xa1 = *(const float4*)&X[grow1 * 128 + kn + xc1];
            wb0 = *(const float4*)&W[(kn + wr0) * 128 + wc0];
            wb1 = *(const float4*)&W[(kn + wr1) * 128 + wc1];
        }
        #pragma unroll
        for (int k = 0; k < 16; k++) {
            float a[8];
            *(float4*)&a[0] = *(const float4*)&As[k][ty * 4];
            *(float4*)&a[4] = *(const float4*)&As[k][64 + ty * 4];
            unsigned long long bp[4];
            bp[0] = *(const unsigned long long*)&Bs[k][tx * 4];
            bp[1] = *(const unsigned long long*)&Bs[k][tx * 4 + 2];
            bp[2] = *(const unsigned long long*)&Bs[k][64 + tx * 4];
            bp[3] = *(const unsigned long long*)&Bs[k][64 + tx * 4 + 2];
            #pragma unroll
            for (int i = 0; i < 8; i++) {
                unsigned long long ap = pack_dup(a[i]);
                #pragma unroll
                for (int j = 0; j < 4; j++) ffma2(accp[i][j], ap, bp[j]);
            }
        }
        __syncthreads();
    }

    float asl[4], adl[4], ash[4], adh[4];
    #pragma unroll
    for (int j = 0; j < 4; j++) {
        asl[j] = a_src[tx * 4 + j];      adl[j] = a_dst[tx * 4 + j];
        ash[j] = a_src[64 + tx * 4 + j]; adh[j] = a_dst[64 + tx * 4 + j];
    }
    #pragma unroll
    for (int i = 0; i < 8; i++) {
        int gr = blockRow + ((i < 4) ? (ty * 4 + i) : (64 + ty * 4 + i - 4));
        if (gr >= N_NODES) continue;
        float2 p0 = unpack2(accp[i][0]), p1 = unpack2(accp[i][1]);
        float2 p2 = unpack2(accp[i][2]), p3 = unpack2(accp[i][3]);
        __half2 q0 = __floats2half2_rn(p0.x, p0.y);
        __half2 q1 = __floats2half2_rn(p1.x, p1.y);
        __half2 q2 = __floats2half2_rn(p2.x, p2.y);
        __half2 q3 = __floats2half2_rn(p3.x, p3.y);
        *(uint2*)&g_h1h[gr * 128 + tx * 4]      = make_uint2(h2_bits(q0), h2_bits(q1));
        *(uint2*)&g_h1h[gr * 128 + 64 + tx * 4] = make_uint2(h2_bits(q2), h2_bits(q3));
        float sl = p0.x * asl[0] + p0.y * asl[1] + p1.x * asl[2] + p1.y * asl[3];
        float dl = p0.x * adl[0] + p0.y * adl[1] + p1.x * adl[2] + p1.y * adl[3];
        float sh = p2.x * ash[0] + p2.y * ash[1] + p3.x * ash[2] + p3.y * ash[3];
        float dh = p2.x * adh[0] + p2.y * adh[1] + p3.x * adh[2] + p3.y * adh[3];
        #pragma unroll
        for (int off = 1; off <= 4; off <<= 1) {
            sl += __shfl_xor_sync(FULLMASK, sl, off);
            dl += __shfl_xor_sync(FULLMASK, dl, off);
            sh += __shfl_xor_sync(FULLMASK, sh, off);
            dh += __shfl_xor_sync(FULLMASK, dh, off);
        }
        if ((tx & 7) == 0) {
            int hl = tx >> 3;
            g_as1[gr * 4 + hl] = sl;       g_ad1[gr * 4 + hl] = dl;
            g_as1[gr * 4 + 2 + hl] = sh;   g_ad1[gr * 4 + 2 + hl] = dh;
        }
    }
}

// ---- layer-1 aggregation: warp per dst node; fp16 gather; deg<=32 fast path
__global__ __launch_bounds__(256) void agg1_kernel(const float* __restrict__ b1,
                                                   int node0, int nnodes) {
    __shared__ float sw[8][2][32][4];
    __shared__ int   ss[8][2][32];
    int warpid = threadIdx.x >> 5;
    int lane = threadIdx.x & 31;
    int n = node0 + blockIdx.x * 8 + warpid;
    if (n >= node0 + nnodes) return;
    int s0 = g_rowstart[n], s1 = g_rowstart[n + 1];
    int deg = s1 - s0;
    float4 ad = *(const float4*)&g_ad1[n * 4];

    float m0, m1, m2, m3, d0, d1, d2, d3;
    float acc0 = 0.f, acc1 = 0.f, acc2 = 0.f, acc3 = 0.f;
    int hsel = lane >> 3;

    if (deg <= 32) {
        // fast path: one chunk; as1 read once, e-values staged in smem
        int e = s0 + lane;
        bool act = (e < s1);
        int sl = 0;
        float4 ev = make_float4(-1e30f, -1e30f, -1e30f, -1e30f);
        if (act) {
            sl = g_srcs[e];
            float4 a = *(const float4*)&g_as1[sl * 4];
            ev = make_float4(lrelu(a.x + ad.x), lrelu(a.y + ad.y),
                             lrelu(a.z + ad.z), lrelu(a.w + ad.w));
            ss[warpid][0][lane] = sl;
        }
        m0 = ev.x; m1 = ev.y; m2 = ev.z; m3 = ev.w;
        d0 = act ? 1.f : 0.f; d1 = d0; d2 = d0; d3 = d0;
        #pragma unroll
        for (int off = 16; off >= 1; off >>= 1) {
            float om, od, nm;
            om = __shfl_xor_sync(FULLMASK, m0, off); od = __shfl_xor_sync(FULLMASK, d0, off);
            nm = fmaxf(m0, om); d0 = d0 * __expf(m0 - nm) + od * __expf(om - nm); m0 = nm;
            om = __shfl_xor_sync(FULLMASK, m1, off); od = __shfl_xor_sync(FULLMASK, d1, off);
            nm = fmaxf(m1, om); d1 = d1 * __expf(m1 - nm) + od * __expf(om - nm); m1 = nm;
            om = __shfl_xor_sync(FULLMASK, m2, off); od = __shfl_xor_sync(FULLMASK, d2, off);
            nm = fmaxf(m2, om); d2 = d2 * __expf(m2 - nm) + od * __expf(om - nm); m2 = nm;
            om = __shfl_xor_sync(FULLMASK, m3, off); od = __shfl_xor_sync(FULLMASK, d3, off);
            nm = fmaxf(m3, om); d3 = d3 * __expf(m3 - nm) + od * __expf(om - nm); m3 = nm;
        }
        float r0 = 1.f / d0, r1 = 1.f / d1, r2 = 1.f / d2, r3 = 1.f / d3;
        if (act) {
            sw[warpid][0][lane][0] = __expf(ev.x - m0) * r0;
            sw[warpid][0][lane][1] = __expf(ev.y - m1) * r1;
            sw[warpid][0][lane][2] = __expf(ev.z - m2) * r2;
            sw[warpid][0][lane][3] = __expf(ev.w - m3) * r3;
        }
        __syncwarp();
        #pragma unroll 4
        for (int j = 0; j < deg; j++) {
            int s = ss[warpid][0][j];
            float wsel = sw[warpid][0][j][hsel];
            uint2 hraw = *(const uint2*)&g_h1h[s * 128 + lane * 4];
            float2 h01 = __half22float2(*(__half2*)&hraw.x);
            float2 h23 = __half22float2(*(__half2*)&hraw.y);
            acc0 = fmaf(h01.x, wsel, acc0);
            acc1 = fmaf(h01.y, wsel, acc1);
            acc2 = fmaf(h23.x, wsel, acc2);
            acc3 = fmaf(h23.y, wsel, acc3);
        }
    } else {
        // general path (rare): online softmax + double-buffered chunks
        m0 = -1e30f; m1 = -1e30f; m2 = -1e30f; m3 = -1e30f;
        d0 = 0.f; d1 = 0.f; d2 = 0.f; d3 = 0.f;
        for (int e = s0 + lane; e < s1; e += 32) {
            int s = g_srcs[e];
            float4 a = *(const float4*)&g_as1[s * 4];
            float e0 = lrelu(a.x + ad.x), e1 = lrelu(a.y + ad.y);
            float e2 = lrelu(a.z + ad.z), e3 = lrelu(a.w + ad.w);
            float nm;
            nm = fmaxf(m0, e0); d0 = d0 * __expf(m0 - nm) + __expf(e0 - nm); m0 = nm;
            nm = fmaxf(m1, e1); d1 = d1 * __expf(m1 - nm) + __expf(e1 - nm); m1 = nm;
            nm = fmaxf(m2, e2); d2 = d2 * __expf(m2 - nm) + __expf(e2 - nm); m2 = nm;
            nm = fmaxf(m3, e3); d3 = d3 * __expf(m3 - nm) + __expf(e3 - nm); m3 = nm;
        }
        #pragma unroll
        for (int off = 16; off >= 1; off >>= 1) {
            float om, od, nm;
            om = __shfl_xor_sync(FULLMASK, m0, off); od = __shfl_xor_sync(FULLMASK, d0, off);
            nm = fmaxf(m0, om); d0 = d0 * __expf(m0 - nm) + od * __expf(om - nm); m0 = nm;
            om = __shfl_xor_sync(FULLMASK, m1, off); od = __shfl_xor_sync(FULLMASK, d1, off);
            nm = fmaxf(m1, om); d1 = d1 * __expf(m1 - nm) + od * __expf(om - nm); m1 = nm;
            om = __shfl_xor_sync(FULLMASK, m2, off); od = __shfl_xor_sync(FULLMASK, d2, off);
            nm = fmaxf(m2, om); d2 = d2 * __expf(m2 - nm) + od * __expf(om - nm); m2 = nm;
            om = __shfl_xor_sync(FULLMASK, m3, off); od = __shfl_xor_sync(FULLMASK, d3, off);
            nm = fmaxf(m3, om); d3 = d3 * __expf(m3 - nm) + od * __expf(om - nm); m3 = nm;
        }
        float r0 = 1.f / d0, r1 = 1.f / d1, r2 = 1.f / d2, r3 = 1.f / d3;
        int buf = 0;
        {
            int e = s0 + lane;
            if (e < s1) {
                int sl = g_srcs[e];
                float4 a = *(const float4*)&g_as1[sl * 4];
                sw[warpid][0][lane][0] = __expf(lrelu(a.x + ad.x) - m0) * r0;
                sw[warpid][0][lane][1] = __expf(lrelu(a.y + ad.y) - m1) * r1;
                sw[warpid][0][lane][2] = __expf(lrelu(a.z + ad.z) - m2) * r2;
                sw[warpid][0][lane][3] = __expf(lrelu(a.w + ad.w) - m3) * r3;
                ss[warpid][0][lane] = sl;
            }
        }
        __syncwarp();
        for (int base = s0; base < s1; base += 32) {
            int nb = base + 32;
            if (nb < s1) {
                int e = nb + lane;
                if (e < s1) {
                    int sl = g_srcs[e];
                    float4 a = *(const float4*)&g_as1[sl * 4];
                    sw[warpid][buf ^ 1][lane][0] = __expf(lrelu(a.x + ad.x) - m0) * r0;
                    sw[warpid][buf ^ 1][lane][1] = __expf(lrelu(a.y + ad.y) - m1) * r1;
                    sw[warpid][buf ^ 1][lane][2] = __expf(lrelu(a.z + ad.z) - m2) * r2;
                    sw[warpid][buf ^ 1][lane][3] = __expf(lrelu(a.w + ad.w) - m3) * r3;
                    ss[warpid][buf ^ 1][lane] = sl;
                }
            }
            int cnt = min(32, s1 - base);
            #pragma unroll 4
            for (int j = 0; j < cnt; j++) {
                int s = ss[warpid][buf][j];
                float wsel = sw[warpid][buf][j][hsel];
                uint2 hraw = *(const uint2*)&g_h1h[s * 128 + lane * 4];
                float2 h01 = __half22float2(*(__half2*)&hraw.x);
                float2 h23 = __half22float2(*(__half2*)&hraw.y);
                acc0 = fmaf(h01.x, wsel, acc0);
                acc1 = fmaf(h01.y, wsel, acc1);
                acc2 = fmaf(h23.x, wsel, acc2);
                acc3 = fmaf(h23.y, wsel, acc3);
            }
            __syncwarp();
            buf ^= 1;
        }
    }
    float4 bb = *(const float4*)&b1[lane * 4];
    *(float4*)&g_out1[n * 128 + lane * 4] =
        make_float4(fmaxf(acc0 + bb.x, 0.f), fmaxf(acc1 + bb.y, 0.f),
                    fmaxf(acc2 + bb.z, 0.f), fmaxf(acc3 + bb.w, 0.f));
}

// ---- GEMM2: 128 threads, 8x8 thread tiles, single wave, fused alpha2 -------
__global__ __launch_bounds__(128, 4) void gemm2_kernel(const float* __restrict__ W,
                                                       const float* __restrict__ a_src,
                                                       const float* __restrict__ a_dst,
                                                       int rowBase) {
    __shared__ __align__(16) float As[16][132];
    __shared__ __align__(16) float Bs[16][64];
    int tid = threadIdx.x;
    int tx = tid & 7, ty = tid >> 3;          // tx 0..7 (cols), ty 0..15 (rows)
    int blockRow = rowBase + blockIdx.x * 128;
    unsigned long long accp[8][4];
    #pragma unroll
    for (int i = 0; i < 8; i++)
        #pragma unroll
        for (int j = 0; j < 4; j++) accp[i][j] = 0ull;

    // A loader: 4 float4 per thread (128x16 tile), B loader: 2 float4 (16x64)
    int axr[4], axc[4];
    #pragma unroll
    for (int l = 0; l < 4; l++) {
        int id = tid * 4 + l;
        axr[l] = id >> 2; axc[l] = (id & 3) * 4;
    }
    int bwr0 = (tid * 2) >> 4,     bwc0 = ((tid * 2) & 15) * 4;
    int bwr1 = (tid * 2 + 1) >> 4, bwc1 = ((tid * 2 + 1) & 15) * 4;

    float4 xa[4], wb0, wb1;
    #pragma unroll
    for (int l = 0; l < 4; l++) {
        int gr = blockRow + axr[l];
        xa[l] = (gr < N_NODES) ? *(const float4*)&g_out1[gr * 128 + axc[l]]
                               : make_float4(0, 0, 0, 0);
    }
    wb0 = *(const float4*)&W[bwr0 * 64 + bwc0];
    wb1 = *(const float4*)&W[bwr1 * 64 + bwc1];

    for (int k0 = 0; k0 < 128; k0 += 16) {
        #pragma unroll
        for (int l = 0; l < 4; l++) {
            As[axc[l] + 0][axr[l]] = xa[l].x; As[axc[l] + 1][axr[l]] = xa[l].y;
            As[axc[l] + 2][axr[l]] = xa[l].z; As[axc[l] + 3][axr[l]] = xa[l].w;
        }
        *(float4*)&Bs[bwr0][bwc0] = wb0;
        *(float4*)&Bs[bwr1][bwc1] = wb1;
        __syncthreads();
        if (k0 + 16 < 128) {
            int kn = k0 + 16;
            #pragma unroll
            for (int l = 0; l < 4; l++) {
                int gr = blockRow + axr[l];
                xa[l] = (gr < N_NODES) ? *(const float4*)&g_out1[gr * 128 + kn + axc[l]]
                                       : make_float4(0, 0, 0, 0);
            }
            wb0 = *(const float4*)&W[(kn + bwr0) * 64 + bwc0];
            wb1 = *(const float4*)&W[(kn + bwr1) * 64 + bwc1];
        }
        #pragma unroll
        for (int k = 0; k < 16; k++) {
            float a[8];
            *(float4*)&a[0] = *(const float4*)&As[k][ty * 4];
            *(float4*)&a[4] = *(const float4*)&As[k][64 + ty * 4];
            unsigned long long bp[4];
            bp[0] = *(const unsigned long long*)&Bs[k][tx * 4];
            bp[1] = *(const unsigned long long*)&Bs[k][tx * 4 + 2];
            bp[2] = *(const unsigned long long*)&Bs[k][32 + tx * 4];
            bp[3] = *(const unsigned long long*)&Bs[k][32 + tx * 4 + 2];
            #pragma unroll
            for (int i = 0; i < 8; i++) {
                unsigned long long ap = pack_dup(a[i]);
                #pragma unroll
                for (int j = 0; j < 4; j++) ffma2(accp[i][j], ap, bp[j]);
            }
        }
        __syncthreads();
    }

    float asl[4], ash[4], adl[4], adh[4];
    #pragma unroll
    for (int j = 0; j < 4; j++) {
        asl[j] = a_src[tx * 4 + j];      adl[j] = a_dst[tx * 4 + j];
        ash[j] = a_src[32 + tx * 4 + j]; adh[j] = a_dst[32 + tx * 4 + j];
    }
    #pragma unroll
    for (int i = 0; i < 8; i++) {
        int gr = blockRow + ((i < 4) ? (ty * 4 + i) : (64 + ty * 4 + i - 4));
        if (gr >= N_NODES) continue;
        float2 p0 = unpack2(accp[i][0]), p1 = unpack2(accp[i][1]);
        float2 p2 = unpack2(accp[i][2]), p3 = unpack2(accp[i][3]);
        __half2 q0 = __floats2half2_rn(p0.x, p0.y);
        __half2 q1 = __floats2half2_rn(p1.x, p1.y);
        __half2 q2 = __floats2half2_rn(p2.x, p2.y);
        __half2 q3 = __floats2half2_rn(p3.x, p3.y);
        *(uint2*)&g_h2h[gr * 64 + tx * 4]      = make_uint2(h2_bits(q0), h2_bits(q1));
        *(uint2*)&g_h2h[gr * 64 + 32 + tx * 4] = make_uint2(h2_bits(q2), h2_bits(q3));
        float ps = p0.x * asl[0] + p0.y * asl[1] + p1.x * asl[2] + p1.y * asl[3]
                 + p2.x * ash[0] + p2.y * ash[1] + p3.x * ash[2] + p3.y * ash[3];
        float pd = p0.x * adl[0] + p0.y * adl[1] + p1.x * adl[2] + p1.y * adl[3]
                 + p2.x * adh[0] + p2.y * adh[1] + p3.x * adh[2] + p3.y * adh[3];
        #pragma unroll
        for (int off = 1; off <= 4; off <<= 1) {   // reduce over 8-lane group (tx)
            ps += __shfl_xor_sync(FULLMASK, ps, off);
            pd += __shfl_xor_sync(FULLMASK, pd, off);
        }
        if (tx == 0) { g_as2[gr] = ps; g_ad2[gr] = pd; }
    }
}

// ---- layer-2 aggregation: warp per dst node; fp16 gather; deg<=32 fast path
__global__ __launch_bounds__(256) void agg2_kernel(const float* __restrict__ b2,
                                                   float* __restrict__ out) {
    __shared__ float sw[8][2][32];
    __shared__ int   ss[8][2][32];
    int warpid = threadIdx.x >> 5;
    int lane = threadIdx.x & 31;
    int n = blockIdx.x * 8 + warpid;
    if (n >= N_NODES) return;
    int s0 = g_rowstart[n], s1 = g_rowstart[n + 1];
    int deg = s1 - s0;
    float ad = g_ad2[n];
    float acc0 = 0.f, acc1 = 0.f;

    if (deg <= 32) {
        int e = s0 + lane;
        bool act = (e < s1);
        int sl = 0;
        float ev = -1e30f;
        if (act) {
            sl = g_srcs[e];
            ev = lrelu(g_as2[sl] + ad);
            ss[warpid][0][lane] = sl;
        }
        float m = ev, d = act ? 1.f : 0.f;
        #pragma unroll
        for (int off = 16; off >= 1; off >>= 1) {
            float om = __shfl_xor_sync(FULLMASK, m, off);
            float od = __shfl_xor_sync(FULLMASK, d, off);
            float nm = fmaxf(m, om);
            d = d * __expf(m - nm) + od * __expf(om - nm);
            m = nm;
        }
        float rd = 1.f / d;
        if (act) sw[warpid][0][lane] = __expf(ev - m) * rd;
        __syncwarp();
        #pragma unroll 4
        for (int j = 0; j < deg; j++) {
            float wj = sw[warpid][0][j];
            int s = ss[warpid][0][j];
            uint32_t hraw = *(const uint32_t*)&g_h2h[s * 64 + lane * 2];
            float2 h = __half22float2(*(__half2*)&hraw);
            acc0 = fmaf(h.x, wj, acc0);
            acc1 = fmaf(h.y, wj, acc1);
        }
    } else {
        float m = -1e30f, d = 0.f;
        for (int e = s0 + lane; e < s1; e += 32) {
            float ev = lrelu(g_as2[g_srcs[e]] + ad);
            float nm = fmaxf(m, ev);
            d = d * __expf(m - nm) + __expf(ev - nm);
            m = nm;
        }
        #pragma unroll
        for (int off = 16; off >= 1; off >>= 1) {
            float om = __shfl_xor_sync(FULLMASK, m, off);
            float od = __shfl_xor_sync(FULLMASK, d, off);
            float nm = fmaxf(m, om);
            d = d * __expf(m - nm) + od * __expf(om - nm);
            m = nm;
        }
        float rd = 1.f / d;
        int buf = 0;
        {
            int e = s0 + lane;
            if (e < s1) {
                int sl = g_srcs[e];
                sw[warpid][0][lane] = __expf(lrelu(g_as2[sl] + ad) - m) * rd;
                ss[warpid][0][lane] = sl;
            }
        }
        __syncwarp();
        for (int base = s0; base < s1; base += 32) {
            int nb = base + 32;
            if (nb < s1) {
                int e = nb + lane;
                if (e < s1) {
                    int sl = g_srcs[e];
                    sw[warpid][buf ^ 1][lane] = __expf(lrelu(g_as2[sl] + ad) - m) * rd;
                    ss[warpid][buf ^ 1][lane] = sl;
                }
            }
            int cnt = min(32, s1 - base);
            #pragma unroll 4
            for (int j = 0; j < cnt; j++) {
                float wj = sw[warpid][buf][j];
                int s = ss[warpid][buf][j];
                uint32_t hraw = *(const uint32_t*)&g_h2h[s * 64 + lane * 2];
                float2 h = __half22float2(*(__half2*)&hraw);
                acc0 = fmaf(h.x, wj, acc0);
                acc1 = fmaf(h.y, wj, acc1);
            }
            __syncwarp();
            buf ^= 1;
        }
    }
    float2 bb = *(const float2*)&b2[lane * 2];
    *(float2*)&out[n * 64 + lane * 2] = make_float2(acc0 + bb.x, acc1 + bb.y);
}

// ---------------- launcher ----------------
extern "C" void kernel_launch(void* const* d_in, const int* in_sizes, int n_in,
                              void* d_out, int out_size) {
    const float* x      = (const float*)d_in[0];
    const int*   ei     = (const int*)d_in[1];   // int32 (JAX x64 disabled)
    // d_in[2] edge_weight unused (PyG GATConv ignores it with edge_dim unset)
    const float* W1     = (const float*)d_in[3];
    const float* a_src1 = (const float*)d_in[4];
    const float* a_dst1 = (const float*)d_in[5];
    const float* b1     = (const float*)d_in[6];
    const float* W2     = (const float*)d_in[7];
    const float* a_src2 = (const float*)d_in[8];
    const float* a_dst2 = (const float*)d_in[9];
    const float* b2     = (const float*)d_in[10];
    float*       out    = (float*)d_out;

    static cudaStream_t s2 = nullptr;
    static cudaEvent_t evFork = nullptr, evJoin = nullptr, evA = nullptr, evG2a = nullptr;
    static void* degPtr = nullptr;
    if (s2 == nullptr) {
        cudaStreamCreateWithFlags(&s2, cudaStreamNonBlocking);
        cudaEventCreateWithFlags(&evFork, cudaEventDisableTiming);
        cudaEventCreateWithFlags(&evJoin, cudaEventDisableTiming);
        cudaEventCreateWithFlags(&evA, cudaEventDisableTiming);
        cudaEventCreateWithFlags(&evG2a, cudaEventDisableTiming);
        cudaGetSymbolAddress(&degPtr, g_deg);
    }

    // fork: CSR build on side stream, overlapped with GEMM1
    cudaEventRecord(evFork, 0);
    cudaStreamWaitEvent(s2, evFork, 0);
    cudaMemsetAsync(degPtr, 0, N_NODES * sizeof(int), s2);
    build_deg_kernel<<<(E_TOT / 4 + 255) / 256, 256, 0, s2>>>(ei);
    scan1_kernel<<<NBLK, 256, 0, s2>>>();
    scan2_kernel<<<1, 256, 0, s2>>>();
    scan3_kernel<<<NBLK, 256, 0, s2>>>();
    scatter_kernel<<<(E_TOT / 4 + 255) / 256, 256, 0, s2>>>(ei);
    cudaEventRecord(evJoin, s2);

    gemm1_kernel<<<(N_NODES + 127) / 128, 256>>>(x, W1, a_src1, a_dst1);

    // join: agg1 needs the CSR
    cudaStreamWaitEvent(0, evJoin, 0);

    // agg1 half A -> (side stream) gemm2 half A overlapped with agg1 half B
    agg1_kernel<<<N_HALF / 8, 256>>>(b1, 0, N_HALF);
    cudaEventRecord(evA, 0);
    agg1_kernel<<<(N_NODES - N_HALF + 7) / 8, 256>>>(b1, N_HALF, N_NODES - N_HALF);

    cudaStreamWaitEvent(s2, evA, 0);
    gemm2_kernel<<<N_HALF / 128, 128, 0, s2>>>(W2, a_src2, a_dst2, 0);
    cudaEventRecord(evG2a, s2);

    gemm2_kernel<<<(N_NODES - N_HALF + 127) / 128, 128>>>(W2, a_src2, a_dst2, N_HALF);

    // agg2 needs both gemm2 halves
    cudaStreamWaitEvent(0, evG2a, 0);
    agg2_kernel<<<(N_NODES + 7) / 8, 256>>>(b2, out);
}